// round 9
// baseline (speedup 1.0000x reference)
#include <cuda_runtime.h>
#include <cuda_fp16.h>
#include <cstdint>

#define IN_F   128
#define HID_F  128
#define OUT_F  64
#define MAX_N  100000
#define MAX_E  1600000

// ---------------- scratch (static device memory; no allocations) ----------------
__device__ float  g_dinv  [MAX_N];
__device__ int    g_cnt   [MAX_N];
__device__ int    g_rowptr[MAX_N + 1];
__device__ int    g_pos   [MAX_N];
__device__ int2   g_ecol  [MAX_E];         // .x = src id, .y = coef (float bits)
__device__ int    g_bsum  [512];
__device__ __half g_h0h   [(size_t)MAX_N * HID_F];   // x @ W1            (fp16)
__device__ __half g_aggh  [(size_t)MAX_N * HID_F];   // relu(conv1 out)   (fp16)
__device__ __half g_h2h   [(size_t)MAX_N * OUT_F];   // h @ W2            (fp16)
__device__ int    g_is64;

// ---------------- zero counts + edge-index dtype detection ----------------------
__global__ void init_zero_detect(const unsigned int* __restrict__ w, int n) {
    int i = blockIdx.x * blockDim.x + threadIdx.x;
    if (i < n) g_cnt[i] = 0;
    if (i == 0) {
        int is64 = 1;
        for (int j = 1; j < 64; j += 2)
            if (w[j] != 0u) is64 = 0;
        g_is64 = is64;
    }
}

__device__ __forceinline__ void load_edge(const void* ei, int E, int i, int is64,
                                          int& s, int& d) {
    if (is64) {
        s = (int)((const long long*)ei)[i];
        d = (int)((const long long*)ei)[(size_t)E + i];
    } else {
        s = ((const int*)ei)[i];
        d = ((const int*)ei)[(size_t)E + i];
    }
}

__global__ void count_kernel(const void* __restrict__ ei, int E) {
    const int is64 = g_is64;
    int i = blockIdx.x * blockDim.x + threadIdx.x;
    if (i < E) {
        int d = is64 ? (int)((const long long*)ei)[(size_t)E + i]
                     : ((const int*)ei)[(size_t)E + i];
        atomicAdd(&g_cnt[d], 1);
    }
}

// ---------------- CSR scan chain ------------------------------------------------
__global__ void scan_block(int n) {
    __shared__ int sh[256];
    int tid = threadIdx.x;
    int i = blockIdx.x * 256 + tid;
    int v = (i < n) ? g_cnt[i] : 0;
    sh[tid] = v;
    __syncthreads();
#pragma unroll
    for (int off = 1; off < 256; off <<= 1) {
        int t = (tid >= off) ? sh[tid - off] : 0;
        __syncthreads();
        sh[tid] += t;
        __syncthreads();
    }
    if (i < n) g_rowptr[i] = sh[tid] - v;
    if (tid == 255) g_bsum[blockIdx.x] = sh[255];
}

// merged top-scan + add: block offset = sum of g_bsum[0..blockIdx)
__global__ void scan_add(int n, int E) {
    __shared__ int red[8];
    __shared__ int offsh;
    int tid = threadIdx.x;
    int v = 0;
    for (int j = tid; j < blockIdx.x; j += 256) v += g_bsum[j];
#pragma unroll
    for (int o = 16; o; o >>= 1) v += __shfl_down_sync(0xffffffffu, v, o);
    if ((tid & 31) == 0) red[tid >> 5] = v;
    __syncthreads();
    if (tid == 0) {
        int s = 0;
#pragma unroll
        for (int j = 0; j < 8; j++) s += red[j];
        offsh = s;
    }
    __syncthreads();
    int off = offsh;
    int i = blockIdx.x * 256 + tid;
    if (i < n) {
        int r = g_rowptr[i] + off;
        g_rowptr[i] = r;
        g_pos[i] = r;
        g_dinv[i] = rsqrtf((float)g_cnt[i] + 1.0f);
    }
    if (i == 0) g_rowptr[n] = E;
}

__global__ void fill_kernel(const void* __restrict__ ei, int E) {
    const int is64 = g_is64;
    int i = blockIdx.x * blockDim.x + threadIdx.x;
    if (i < E) {
        int s, d; load_edge(ei, E, i, is64, s, d);
        int idx = atomicAdd(&g_pos[d], 1);
        float coef = g_dinv[s] * g_dinv[d];
        g_ecol[idx] = make_int2(s, __float_as_int(coef));
    }
}

// ---------------- tf32 helper ----------------------------------------------------
__device__ __forceinline__ unsigned f2tf32(float f) {
    unsigned u;
    asm("cvt.rna.tf32.f32 %0, %1;" : "=r"(u) : "f"(f));
    return u;
}

// ---------------- TF32 tensor-core GEMM ------------------------------------------
// C[M,NC] = A[M,K] @ W[K,NC] (+bias), fp32 accumulate. 64-row tiles,
// 8 warps = 2 m-groups (2 m-subtiles each) x 4 n-groups; B-frags reused.
// A_HALF: A is fp16 (exact cvt to tf32). OUT_HALF: C written fp16.
template<int K, int NC, bool A_HALF, bool OUT_HALF, bool BIAS>
__global__ void __launch_bounds__(256) gemm_tc(
        const void* __restrict__ Av, const float* __restrict__ W,
        const float* __restrict__ bias, void* __restrict__ Cv, int M) {
    constexpr int KP   = K + 4;
    constexpr int NCP  = NC + 8;
    constexpr int NT_W = NC / 32;

    extern __shared__ unsigned sh[];
    unsigned* Ws = sh;                 // K * NCP
    unsigned* As = sh + K * NCP;       // 64 * KP

    const int tid = threadIdx.x;

    for (int i = tid; i < K * NC / 4; i += 256) {
        int k = i / (NC / 4), n4 = i - k * (NC / 4);
        float4 v = ((const float4*)W)[i];
        uint4 u = {f2tf32(v.x), f2tf32(v.y), f2tf32(v.z), f2tf32(v.w)};
        *(uint4*)(Ws + k * NCP + n4 * 4) = u;
    }

    const int warp = tid >> 5, lane = tid & 31;
    const int g = lane >> 2, tg = lane & 3;
    const int mi = warp >> 2;
    const int ni = warp & 3;
    const int ntiles = (M + 63) >> 6;

    for (int tile = blockIdx.x; tile < ntiles; tile += gridDim.x) {
        const int row0 = tile << 6;
        __syncthreads();
        // ---- stage 64-row A tile ----
        if (A_HALF) {
            const __half* A = (const __half*)Av;
            constexpr int K8 = K / 8;
            for (int i = tid; i < 64 * K8; i += 256) {
                int r = i / K8, c8 = i - r * K8;
                float f[8];
                if (row0 + r < M) {
                    uint4 u = *(const uint4*)(A + (size_t)(row0 + r) * K + c8 * 8);
                    const __half2* hp = (const __half2*)&u;
#pragma unroll
                    for (int q = 0; q < 4; q++) {
                        float2 f2 = __half22float2(hp[q]);
                        f[2 * q] = f2.x; f[2 * q + 1] = f2.y;
                    }
                } else {
#pragma unroll
                    for (int q = 0; q < 8; q++) f[q] = 0.f;
                }
                unsigned* dst = As + r * KP + c8 * 8;
                uint4 u0 = {f2tf32(f[0]), f2tf32(f[1]), f2tf32(f[2]), f2tf32(f[3])};
                uint4 u1 = {f2tf32(f[4]), f2tf32(f[5]), f2tf32(f[6]), f2tf32(f[7])};
                *(uint4*)dst = u0;
                *(uint4*)(dst + 4) = u1;
            }
        } else {
            const float* A = (const float*)Av;
            constexpr int K4 = K / 4;
            for (int i = tid; i < 64 * K4; i += 256) {
                int r = i / K4, c4 = i - r * K4;
                float4 v = {0.f, 0.f, 0.f, 0.f};
                if (row0 + r < M) v = *(const float4*)(A + (size_t)(row0 + r) * K + c4 * 4);
                uint4 u = {f2tf32(v.x), f2tf32(v.y), f2tf32(v.z), f2tf32(v.w)};
                *(uint4*)(As + r * KP + c4 * 4) = u;
            }
        }
        __syncthreads();

        float acc[2][NT_W][4];
#pragma unroll
        for (int ms = 0; ms < 2; ms++)
#pragma unroll
            for (int t = 0; t < NT_W; t++)
#pragma unroll
                for (int v = 0; v < 4; v++) acc[ms][t][v] = 0.f;

        const unsigned* Arow0 = As + (mi * 32 + g) * KP;
        const unsigned* Arow1 = Arow0 + 16 * KP;
#pragma unroll
        for (int k0 = 0; k0 < K; k0 += 8) {
            unsigned a[2][4];
            a[0][0] = Arow0[k0 + tg];
            a[0][1] = Arow0[8 * KP + k0 + tg];
            a[0][2] = Arow0[k0 + tg + 4];
            a[0][3] = Arow0[8 * KP + k0 + tg + 4];
            a[1][0] = Arow1[k0 + tg];
            a[1][1] = Arow1[8 * KP + k0 + tg];
            a[1][2] = Arow1[k0 + tg + 4];
            a[1][3] = Arow1[8 * KP + k0 + tg + 4];
#pragma unroll
            for (int t = 0; t < NT_W; t++) {
                int n0 = ni * (NT_W * 8) + t * 8;
                unsigned b0 = Ws[(k0 + tg) * NCP + n0 + g];
                unsigned b1 = Ws[(k0 + tg + 4) * NCP + n0 + g];
#pragma unroll
                for (int ms = 0; ms < 2; ms++) {
                    asm volatile(
                        "mma.sync.aligned.m16n8k8.row.col.f32.tf32.tf32.f32 "
                        "{%0,%1,%2,%3},{%4,%5,%6,%7},{%8,%9},{%0,%1,%2,%3};\n"
                        : "+f"(acc[ms][t][0]), "+f"(acc[ms][t][1]),
                          "+f"(acc[ms][t][2]), "+f"(acc[ms][t][3])
                        : "r"(a[ms][0]), "r"(a[ms][1]), "r"(a[ms][2]), "r"(a[ms][3]),
                          "r"(b0), "r"(b1));
                }
            }
        }

#pragma unroll
        for (int ms = 0; ms < 2; ms++) {
            const int r0 = row0 + mi * 32 + ms * 16 + g;
            const int r1 = r0 + 8;
#pragma unroll
            for (int t = 0; t < NT_W; t++) {
                int n0 = ni * (NT_W * 8) + t * 8 + 2 * tg;
                float bx = 0.f, by = 0.f;
                if (BIAS) { bx = bias[n0]; by = bias[n0 + 1]; }
                if (OUT_HALF) {
                    __half* C = (__half*)Cv;
                    if (r0 < M)
                        *(__half2*)(C + (size_t)r0 * NC + n0) =
                            __floats2half2_rn(acc[ms][t][0] + bx, acc[ms][t][1] + by);
                    if (r1 < M)
                        *(__half2*)(C + (size_t)r1 * NC + n0) =
                            __floats2half2_rn(acc[ms][t][2] + bx, acc[ms][t][3] + by);
                } else {
                    float* C = (float*)Cv;
                    if (r0 < M) {
                        float2 o = {acc[ms][t][0] + bx, acc[ms][t][1] + by};
                        *(float2*)(C + (size_t)r0 * NC + n0) = o;
                    }
                    if (r1 < M) {
                        float2 o = {acc[ms][t][2] + bx, acc[ms][t][3] + by};
                        *(float2*)(C + (size_t)r1 * NC + n0) = o;
                    }
                }
            }
        }
    }
}

// ------------- CSR gather aggregation (warp per destination row, fp16 source) ---
// out[i] = sum_nbr h[s]*coef + h[i]*dinv^2 + bias ; optional relu.
template<int F, bool RELU, bool OUT_HALF>
__global__ void __launch_bounds__(256) gather_agg(
        const __half* __restrict__ h, const float* __restrict__ bias,
        void* __restrict__ out, int Nn) {
    int w = (blockIdx.x * 256 + threadIdx.x) >> 5;
    int lane = threadIdx.x & 31;
    if (w >= Nn) return;
    constexpr int V = F / 32;               // halves per lane: 4 or 2

    float dv = g_dinv[w];
    float d2 = dv * dv;
    float acc[V];

    // self-loop + bias
    {
        const __half* hp = h + (size_t)w * F + lane * V;
        if (V == 4) {
            uint2 u = *(const uint2*)hp;
            float2 f0 = __half22float2(*(const __half2*)&u.x);
            float2 f1 = __half22float2(*(const __half2*)&u.y);
            acc[0] = fmaf(f0.x, d2, bias[lane * 4 + 0]);
            acc[1] = fmaf(f0.y, d2, bias[lane * 4 + 1]);
            acc[2] = fmaf(f1.x, d2, bias[lane * 4 + 2]);
            acc[3] = fmaf(f1.y, d2, bias[lane * 4 + 3]);
        } else {
            unsigned u = *(const unsigned*)hp;
            float2 f0 = __half22float2(*(const __half2*)&u);
            acc[0] = fmaf(f0.x, d2, bias[lane * 2 + 0]);
            acc[1] = fmaf(f0.y, d2, bias[lane * 2 + 1]);
        }
    }

    int beg = g_rowptr[w], end = g_rowptr[w + 1];
#pragma unroll 8
    for (int j = beg; j < end; j++) {
        int2 e = g_ecol[j];                 // warp-uniform broadcast load
        float coef = __int_as_float(e.y);
        const __half* hp = h + (size_t)e.x * F + lane * V;
        if (V == 4) {
            uint2 u = *(const uint2*)hp;
            float2 f0 = __half22float2(*(const __half2*)&u.x);
            float2 f1 = __half22float2(*(const __half2*)&u.y);
            acc[0] = fmaf(f0.x, coef, acc[0]); acc[1] = fmaf(f0.y, coef, acc[1]);
            acc[2] = fmaf(f1.x, coef, acc[2]); acc[3] = fmaf(f1.y, coef, acc[3]);
        } else {
            unsigned u = *(const unsigned*)hp;
            float2 f0 = __half22float2(*(const __half2*)&u);
            acc[0] = fmaf(f0.x, coef, acc[0]); acc[1] = fmaf(f0.y, coef, acc[1]);
        }
    }

    if (RELU) {
#pragma unroll
        for (int v = 0; v < V; v++) acc[v] = fmaxf(acc[v], 0.f);
    }

    if (OUT_HALF) {
        __half* op = (__half*)out + (size_t)w * F + lane * V;
        if (V == 4) {
            uint2 u;
            *(__half2*)&u.x = __floats2half2_rn(acc[0], acc[1]);
            *(__half2*)&u.y = __floats2half2_rn(acc[2], acc[3]);
            *(uint2*)op = u;
        } else {
            __half2 u = __floats2half2_rn(acc[0], acc[1]);
            *(__half2*)op = u;
        }
    } else {
        float* op = (float*)out + (size_t)w * F + lane * V;
        if (V == 4) { float4 o = {acc[0], acc[1], acc[2], acc[3]}; *(float4*)op = o; }
        else        { float2 o = {acc[0], acc[1]};                 *(float2*)op = o; }
    }
}

// ---------------- side stream for CSR build (created once, host-side) ------------
struct SideStream {
    cudaStream_t s;
    cudaEvent_t fork, join;
    SideStream() {
        cudaStreamCreateWithFlags(&s, cudaStreamNonBlocking);
        cudaEventCreateWithFlags(&fork, cudaEventDisableTiming);
        cudaEventCreateWithFlags(&join, cudaEventDisableTiming);
    }
};

// --------------------------------- launch ---------------------------------------
extern "C" void kernel_launch(void* const* d_in, const int* in_sizes, int n_in,
                              void* d_out, int out_size) {
    const float* x  = (const float*)d_in[0];
    const void*  ei = d_in[1];
    const float* W1 = (const float*)d_in[2];
    const float* b1 = (const float*)d_in[3];
    const float* W2 = (const float*)d_in[4];
    const float* b2 = (const float*)d_in[5];
    const float* Wd = (const float*)d_in[6];
    const float* bd = (const float*)d_in[7];

    const int N = in_sizes[0] / IN_F;     // 100000
    const int E = in_sizes[1] / 2;        // 1.6M

    float* out = (float*)d_out;           // x_recon [N, IN_F]
    float* z   = out + (size_t)N * IN_F;  // z       [N, OUT_F]

    __half *h0p, *agghp, *h2p;
    cudaGetSymbolAddress((void**)&h0p,   g_h0h);
    cudaGetSymbolAddress((void**)&agghp, g_aggh);
    cudaGetSymbolAddress((void**)&h2p,   g_h2h);

    static SideStream ss;                  // host-side resources, created once

    // smem (bytes): Ws K*(NC+8) + As 64*(K+4), 4B words
    const int smem1 = (IN_F  * (HID_F + 8) + 64 * (IN_F  + 4)) * 4;  // 103424
    const int smem2 = (HID_F * (OUT_F + 8) + 64 * (HID_F + 4)) * 4;  //  70656
    const int smem3 = (OUT_F * (IN_F  + 8) + 64 * (OUT_F + 4)) * 4;  //  52224
    cudaFuncSetAttribute(gemm_tc<IN_F, HID_F, false, true, false>,
                         cudaFuncAttributeMaxDynamicSharedMemorySize, smem1);
    cudaFuncSetAttribute(gemm_tc<HID_F, OUT_F, true, true, false>,
                         cudaFuncAttributeMaxDynamicSharedMemorySize, smem2);
    cudaFuncSetAttribute(gemm_tc<OUT_F, IN_F, false, false, true>,
                         cudaFuncAttributeMaxDynamicSharedMemorySize, smem3);

    const int T = 256;
    const int nScanBlocks = (N + 255) / 256;
    const int aggGrid = (N * 32 + T - 1) / T;     // warp per node

    // zero counts + dtype detect (both branches depend on this)
    init_zero_detect<<<nScanBlocks, 256>>>((const unsigned int*)ei, N);

    // ---- fork: CSR build on side stream, GEMM1 on main stream ----
    cudaEventRecord(ss.fork, 0);
    cudaStreamWaitEvent(ss.s, ss.fork, 0);

    count_kernel<<<(E + T - 1) / T, T, 0, ss.s>>>(ei, E);
    scan_block<<<nScanBlocks, 256, 0, ss.s>>>(N);
    scan_add<<<nScanBlocks, 256, 0, ss.s>>>(N, E);
    fill_kernel<<<(E + T - 1) / T, T, 0, ss.s>>>(ei, E);

    // layer-1 GEMM (fp32 in, fp16 out): h0 = x @ W1   (main stream, concurrent)
    gemm_tc<IN_F, HID_F, false, true, false><<<296, T, smem1>>>(
        x, W1, nullptr, h0p, N);

    cudaEventRecord(ss.join, ss.s);
    cudaStreamWaitEvent(0, ss.join, 0);
    // ---- join ----

    // layer-1 aggregation: aggh = relu(gather(h0) + b1)  (fp16)
    gather_agg<HID_F, true, true><<<aggGrid, T>>>(h0p, b1, agghp, N);

    // layer-2 GEMM (fp16 in, fp16 out): h2 = aggh @ W2
    gemm_tc<HID_F, OUT_F, true, true, false><<<444, T, smem2>>>(
        agghp, W2, nullptr, h2p, N);

    // layer-2 aggregation: z = gather(h2) + b2  (fp32, straight into d_out)
    gather_agg<OUT_F, false, false><<<aggGrid, T>>>(h2p, b2, z, N);

    // decoder (fp32 in from d_out, fp32 out): x_recon = z @ Wd + bd
    gemm_tc<OUT_F, IN_F, false, false, true><<<592, T, smem3>>>(
        z, Wd, bd, out, N);
}

// round 10
// speedup vs baseline: 1.2970x; 1.2970x over previous
#include <cuda_runtime.h>
#include <cuda_fp16.h>
#include <cstdint>

#define IN_F   128
#define HID_F  128
#define OUT_F  64
#define MAX_N  100000
#define MAX_E  1600000

// ---------------- scratch (static device memory; no allocations) ----------------
__device__ float  g_dinv  [MAX_N];
__device__ int    g_cnt   [MAX_N];
__device__ int    g_rowptr[MAX_N + 1];
__device__ int    g_pos   [MAX_N];
__device__ int2   g_ecol  [MAX_E];         // .x = src id, .y = coef (float bits)
__device__ int    g_bsum  [512];
__device__ __half g_h0h   [(size_t)MAX_N * HID_F];   // x @ W1            (fp16)
__device__ __half g_aggh  [(size_t)MAX_N * HID_F];   // relu(conv1 out)   (fp16)
__device__ __half g_h2h   [(size_t)MAX_N * OUT_F];   // h @ W2            (fp16)
__device__ int    g_is64;

// ---------------- zero counts + edge-index dtype detection ----------------------
__global__ void init_zero_detect(const unsigned int* __restrict__ w, int n) {
    int i = blockIdx.x * blockDim.x + threadIdx.x;
    if (i < n) g_cnt[i] = 0;
    if (i == 0) {
        int is64 = 1;
        for (int j = 1; j < 64; j += 2)
            if (w[j] != 0u) is64 = 0;
        g_is64 = is64;
    }
}

__device__ __forceinline__ void load_edge(const void* ei, int E, int i, int is64,
                                          int& s, int& d) {
    if (is64) {
        s = (int)((const long long*)ei)[i];
        d = (int)((const long long*)ei)[(size_t)E + i];
    } else {
        s = ((const int*)ei)[i];
        d = ((const int*)ei)[(size_t)E + i];
    }
}

// ---------------- CSR scan chain ------------------------------------------------
__global__ void scan_block(int n) {
    __shared__ int sh[256];
    int tid = threadIdx.x;
    int i = blockIdx.x * 256 + tid;
    int v = (i < n) ? g_cnt[i] : 0;
    sh[tid] = v;
    __syncthreads();
#pragma unroll
    for (int off = 1; off < 256; off <<= 1) {
        int t = (tid >= off) ? sh[tid - off] : 0;
        __syncthreads();
        sh[tid] += t;
        __syncthreads();
    }
    if (i < n) g_rowptr[i] = sh[tid] - v;
    if (tid == 255) g_bsum[blockIdx.x] = sh[255];
}

// merged top-scan + add: block offset = sum of g_bsum[0..blockIdx)
__global__ void scan_add(int n, int E) {
    __shared__ int red[8];
    __shared__ int offsh;
    int tid = threadIdx.x;
    int v = 0;
    for (int j = tid; j < blockIdx.x; j += 256) v += g_bsum[j];
#pragma unroll
    for (int o = 16; o; o >>= 1) v += __shfl_down_sync(0xffffffffu, v, o);
    if ((tid & 31) == 0) red[tid >> 5] = v;
    __syncthreads();
    if (tid == 0) {
        int s = 0;
#pragma unroll
        for (int j = 0; j < 8; j++) s += red[j];
        offsh = s;
    }
    __syncthreads();
    int off = offsh;
    int i = blockIdx.x * 256 + tid;
    if (i < n) {
        int r = g_rowptr[i] + off;
        g_rowptr[i] = r;
        g_pos[i] = r;
        g_dinv[i] = rsqrtf((float)g_cnt[i] + 1.0f);
    }
    if (i == 0) g_rowptr[n] = E;
}

__global__ void fill_kernel(const void* __restrict__ ei, int E) {
    const int is64 = g_is64;
    int i = blockIdx.x * blockDim.x + threadIdx.x;
    if (i < E) {
        int s, d; load_edge(ei, E, i, is64, s, d);
        int idx = atomicAdd(&g_pos[d], 1);
        float coef = g_dinv[s] * g_dinv[d];
        g_ecol[idx] = make_int2(s, __float_as_int(coef));
    }
}

// ---------------- FP16 tensor-core GEMM ------------------------------------------
// C[M,NC] = A[M,K] @ W[K,NC] (+bias), fp32 accumulate, mma.m16n8k16.f16.f16.f32.
// 64-row tiles; 8 warps = 2 m-groups (2 m-subtiles each) x 4 n-groups.
// SMEM layouts (half2 = 1 word):
//   Ws2[kp][n]  kp=k/2 pair rows, stride NCP2 = NC+8  -> (NCP2 mod 32 == 8, conflict-free)
//   As2[r][kp]  row r, stride KP2 = K/2+4             -> (KP2  mod 32 == 4, conflict-free)
// A_HALF: A is fp16 (raw copy). OUT_HALF: C written fp16. COUNT: degree-count prologue.
template<int K, int NC, bool A_HALF, bool OUT_HALF, bool BIAS, bool COUNT>
__global__ void __launch_bounds__(256) gemm_fp16(
        const void* __restrict__ Av, const float* __restrict__ W,
        const float* __restrict__ bias, void* __restrict__ Cv, int M,
        const void* __restrict__ ei, int E) {
    constexpr int KP2  = K / 2 + 4;
    constexpr int NCP2 = NC + 8;
    constexpr int NT_W = NC / 32;

    extern __shared__ unsigned sh[];
    unsigned* Ws2 = sh;                       // (K/2) * NCP2 words
    unsigned* As2 = sh + (K / 2) * NCP2;      // 64 * KP2 words

    const int tid = threadIdx.x;

    // ---- stage W once: pack k-pairs into half2 words ----
    for (int i = tid; i < (K / 2) * (NC / 4); i += 256) {
        int kp = i / (NC / 4), n4 = i - kp * (NC / 4);
        float4 r0 = *(const float4*)(W + (size_t)(2 * kp) * NC + n4 * 4);
        float4 r1 = *(const float4*)(W + (size_t)(2 * kp + 1) * NC + n4 * 4);
        uint4 u;
        *(__half2*)&u.x = __floats2half2_rn(r0.x, r1.x);
        *(__half2*)&u.y = __floats2half2_rn(r0.y, r1.y);
        *(__half2*)&u.z = __floats2half2_rn(r0.z, r1.z);
        *(__half2*)&u.w = __floats2half2_rn(r0.w, r1.w);
        *(uint4*)(Ws2 + kp * NCP2 + n4 * 4) = u;
    }

    // ---- fused degree count (hidden behind GEMM traffic) ----
    if (COUNT) {
        const int is64 = g_is64;
        for (int i = blockIdx.x * 256 + tid; i < E; i += gridDim.x * 256) {
            int d = is64 ? (int)((const long long*)ei)[(size_t)E + i]
                         : ((const int*)ei)[(size_t)E + i];
            atomicAdd(&g_cnt[d], 1);
        }
    }

    const int warp = tid >> 5, lane = tid & 31;
    const int g = lane >> 2, tg = lane & 3;
    const int mi = warp >> 2;
    const int ni = warp & 3;
    const int ntiles = (M + 63) >> 6;

    for (int tile = blockIdx.x; tile < ntiles; tile += gridDim.x) {
        const int row0 = tile << 6;
        __syncthreads();
        // ---- stage 64-row A tile (8 k-values = 4 half2 words per thread-iter) ----
        constexpr int K8 = K / 8;
        for (int i = tid; i < 64 * K8; i += 256) {
            int r = i / K8, c8 = i - r * K8;
            uint4 u;
            if (A_HALF) {
                const __half* A = (const __half*)Av;
                if (row0 + r < M)
                    u = *(const uint4*)(A + (size_t)(row0 + r) * K + c8 * 8);
                else
                    u = make_uint4(0, 0, 0, 0);
            } else {
                const float* A = (const float*)Av;
                float4 v0 = {0.f, 0.f, 0.f, 0.f}, v1 = {0.f, 0.f, 0.f, 0.f};
                if (row0 + r < M) {
                    v0 = *(const float4*)(A + (size_t)(row0 + r) * K + c8 * 8);
                    v1 = *(const float4*)(A + (size_t)(row0 + r) * K + c8 * 8 + 4);
                }
                *(__half2*)&u.x = __floats2half2_rn(v0.x, v0.y);
                *(__half2*)&u.y = __floats2half2_rn(v0.z, v0.w);
                *(__half2*)&u.z = __floats2half2_rn(v1.x, v1.y);
                *(__half2*)&u.w = __floats2half2_rn(v1.z, v1.w);
            }
            *(uint4*)(As2 + r * KP2 + c8 * 4) = u;
        }
        __syncthreads();

        float acc[2][NT_W][4];
#pragma unroll
        for (int ms = 0; ms < 2; ms++)
#pragma unroll
            for (int t = 0; t < NT_W; t++)
#pragma unroll
                for (int v = 0; v < 4; v++) acc[ms][t][v] = 0.f;

        const unsigned* Arow0 = As2 + (mi * 32 + g) * KP2;
        const unsigned* Arow1 = Arow0 + 16 * KP2;
#pragma unroll
        for (int kp0 = 0; kp0 < K / 2; kp0 += 8) {      // 16 k per iter
            unsigned a[2][4];
            a[0][0] = Arow0[kp0 + tg];
            a[0][1] = Arow0[8 * KP2 + kp0 + tg];
            a[0][2] = Arow0[kp0 + tg + 4];
            a[0][3] = Arow0[8 * KP2 + kp0 + tg + 4];
            a[1][0] = Arow1[kp0 + tg];
            a[1][1] = Arow1[8 * KP2 + kp0 + tg];
            a[1][2] = Arow1[kp0 + tg + 4];
            a[1][3] = Arow1[8 * KP2 + kp0 + tg + 4];
#pragma unroll
            for (int t = 0; t < NT_W; t++) {
                int n0 = ni * (NT_W * 8) + t * 8;
                unsigned b0 = Ws2[(kp0 + tg) * NCP2 + n0 + g];
                unsigned b1 = Ws2[(kp0 + tg + 4) * NCP2 + n0 + g];
#pragma unroll
                for (int ms = 0; ms < 2; ms++) {
                    asm volatile(
                        "mma.sync.aligned.m16n8k16.row.col.f32.f16.f16.f32 "
                        "{%0,%1,%2,%3},{%4,%5,%6,%7},{%8,%9},{%0,%1,%2,%3};\n"
                        : "+f"(acc[ms][t][0]), "+f"(acc[ms][t][1]),
                          "+f"(acc[ms][t][2]), "+f"(acc[ms][t][3])
                        : "r"(a[ms][0]), "r"(a[ms][1]), "r"(a[ms][2]), "r"(a[ms][3]),
                          "r"(b0), "r"(b1));
                }
            }
        }

#pragma unroll
        for (int ms = 0; ms < 2; ms++) {
            const int r0 = row0 + mi * 32 + ms * 16 + g;
            const int r1 = r0 + 8;
#pragma unroll
            for (int t = 0; t < NT_W; t++) {
                int n0 = ni * (NT_W * 8) + t * 8 + 2 * tg;
                float bx = 0.f, by = 0.f;
                if (BIAS) { bx = bias[n0]; by = bias[n0 + 1]; }
                if (OUT_HALF) {
                    __half* C = (__half*)Cv;
                    if (r0 < M)
                        *(__half2*)(C + (size_t)r0 * NC + n0) =
                            __floats2half2_rn(acc[ms][t][0] + bx, acc[ms][t][1] + by);
                    if (r1 < M)
                        *(__half2*)(C + (size_t)r1 * NC + n0) =
                            __floats2half2_rn(acc[ms][t][2] + bx, acc[ms][t][3] + by);
                } else {
                    float* C = (float*)Cv;
                    if (r0 < M) {
                        float2 o = {acc[ms][t][0] + bx, acc[ms][t][1] + by};
                        *(float2*)(C + (size_t)r0 * NC + n0) = o;
                    }
                    if (r1 < M) {
                        float2 o = {acc[ms][t][2] + bx, acc[ms][t][3] + by};
                        *(float2*)(C + (size_t)r1 * NC + n0) = o;
                    }
                }
            }
        }
    }
}

// ------------- CSR gather aggregation (warp per destination row, fp16 source) ---
// out[i] = sum_nbr h[s]*coef + h[i]*dinv^2 + bias ; optional relu.
template<int F, bool RELU, bool OUT_HALF>
__global__ void __launch_bounds__(256) gather_agg(
        const __half* __restrict__ h, const float* __restrict__ bias,
        void* __restrict__ out, int Nn) {
    int w = (blockIdx.x * 256 + threadIdx.x) >> 5;
    int lane = threadIdx.x & 31;
    if (w >= Nn) return;
    constexpr int V = F / 32;               // halves per lane: 4 or 2

    float dv = g_dinv[w];
    float d2 = dv * dv;
    float acc[V];

    // self-loop + bias
    {
        const __half* hp = h + (size_t)w * F + lane * V;
        if (V == 4) {
            uint2 u = *(const uint2*)hp;
            float2 f0 = __half22float2(*(const __half2*)&u.x);
            float2 f1 = __half22float2(*(const __half2*)&u.y);
            acc[0] = fmaf(f0.x, d2, bias[lane * 4 + 0]);
            acc[1] = fmaf(f0.y, d2, bias[lane * 4 + 1]);
            acc[2] = fmaf(f1.x, d2, bias[lane * 4 + 2]);
            acc[3] = fmaf(f1.y, d2, bias[lane * 4 + 3]);
        } else {
            unsigned u = *(const unsigned*)hp;
            float2 f0 = __half22float2(*(const __half2*)&u);
            acc[0] = fmaf(f0.x, d2, bias[lane * 2 + 0]);
            acc[1] = fmaf(f0.y, d2, bias[lane * 2 + 1]);
        }
    }

    int beg = g_rowptr[w], end = g_rowptr[w + 1];
#pragma unroll 8
    for (int j = beg; j < end; j++) {
        int2 e = g_ecol[j];                 // warp-uniform broadcast load
        float coef = __int_as_float(e.y);
        const __half* hp = h + (size_t)e.x * F + lane * V;
        if (V == 4) {
            uint2 u = *(const uint2*)hp;
            float2 f0 = __half22float2(*(const __half2*)&u.x);
            float2 f1 = __half22float2(*(const __half2*)&u.y);
            acc[0] = fmaf(f0.x, coef, acc[0]); acc[1] = fmaf(f0.y, coef, acc[1]);
            acc[2] = fmaf(f1.x, coef, acc[2]); acc[3] = fmaf(f1.y, coef, acc[3]);
        } else {
            unsigned u = *(const unsigned*)hp;
            float2 f0 = __half22float2(*(const __half2*)&u);
            acc[0] = fmaf(f0.x, coef, acc[0]); acc[1] = fmaf(f0.y, coef, acc[1]);
        }
    }

    if (RELU) {
#pragma unroll
        for (int v = 0; v < V; v++) acc[v] = fmaxf(acc[v], 0.f);
    }

    if (OUT_HALF) {
        __half* op = (__half*)out + (size_t)w * F + lane * V;
        if (V == 4) {
            uint2 u;
            *(__half2*)&u.x = __floats2half2_rn(acc[0], acc[1]);
            *(__half2*)&u.y = __floats2half2_rn(acc[2], acc[3]);
            *(uint2*)op = u;
        } else {
            __half2 u = __floats2half2_rn(acc[0], acc[1]);
            *(__half2*)op = u;
        }
    } else {
        float* op = (float*)out + (size_t)w * F + lane * V;
        if (V == 4) { float4 o = {acc[0], acc[1], acc[2], acc[3]}; *(float4*)op = o; }
        else        { float2 o = {acc[0], acc[1]};                 *(float2*)op = o; }
    }
}

// --------------------------------- launch ---------------------------------------
extern "C" void kernel_launch(void* const* d_in, const int* in_sizes, int n_in,
                              void* d_out, int out_size) {
    const float* x  = (const float*)d_in[0];
    const void*  ei = d_in[1];
    const float* W1 = (const float*)d_in[2];
    const float* b1 = (const float*)d_in[3];
    const float* W2 = (const float*)d_in[4];
    const float* b2 = (const float*)d_in[5];
    const float* Wd = (const float*)d_in[6];
    const float* bd = (const float*)d_in[7];

    const int N = in_sizes[0] / IN_F;     // 100000
    const int E = in_sizes[1] / 2;        // 1.6M

    float* out = (float*)d_out;           // x_recon [N, IN_F]
    float* z   = out + (size_t)N * IN_F;  // z       [N, OUT_F]

    __half *h0p, *agghp, *h2p;
    cudaGetSymbolAddress((void**)&h0p,   g_h0h);
    cudaGetSymbolAddress((void**)&agghp, g_aggh);
    cudaGetSymbolAddress((void**)&h2p,   g_h2h);

    // smem (bytes): Ws2 (K/2)*(NC+8) + As2 64*(K/2+4), 4B words
    const int smem1 = ((IN_F  / 2) * (HID_F + 8) + 64 * (IN_F  / 2 + 4)) * 4;  // 52224
    const int smem2 = ((HID_F / 2) * (OUT_F + 8) + 64 * (HID_F / 2 + 4)) * 4;  // 35840
    const int smem3 = ((OUT_F / 2) * (IN_F  + 8) + 64 * (OUT_F / 2 + 4)) * 4;  // 26624
    cudaFuncSetAttribute(gemm_fp16<IN_F, HID_F, false, true, false, true>,
                         cudaFuncAttributeMaxDynamicSharedMemorySize, smem1);
    cudaFuncSetAttribute(gemm_fp16<HID_F, OUT_F, true, true, false, false>,
                         cudaFuncAttributeMaxDynamicSharedMemorySize, smem2);
    cudaFuncSetAttribute(gemm_fp16<OUT_F, IN_F, false, false, true, false>,
                         cudaFuncAttributeMaxDynamicSharedMemorySize, smem3);

    const int T = 256;
    const int nScanBlocks = (N + 255) / 256;
    const int aggGrid = (N * 32 + T - 1) / T;     // warp per node

    // zero counts + dtype detect
    init_zero_detect<<<nScanBlocks, 256>>>((const unsigned int*)ei, N);

    // layer-1 GEMM (fp32 in, fp16 out) with fused degree count: h0 = x @ W1
    gemm_fp16<IN_F, HID_F, false, true, false, true><<<592, T, smem1>>>(
        x, W1, nullptr, h0p, N, ei, E);

    // CSR: block scan -> merged top+add (also dinv) -> fill (per-edge coef)
    scan_block<<<nScanBlocks, 256>>>(N);
    scan_add<<<nScanBlocks, 256>>>(N, E);
    fill_kernel<<<(E + T - 1) / T, T>>>(ei, E);

    // layer-1 aggregation: aggh = relu(gather(h0) + b1)  (fp16)
    gather_agg<HID_F, true, true><<<aggGrid, T>>>(h0p, b1, agghp, N);

    // layer-2 GEMM (fp16 in, fp16 out): h2 = aggh @ W2
    gemm_fp16<HID_F, OUT_F, true, true, false, false><<<592, T, smem2>>>(
        agghp, W2, nullptr, h2p, N, nullptr, 0);

    // layer-2 aggregation: z = gather(h2) + b2  (fp32, straight into d_out)
    gather_agg<OUT_F, false, false><<<aggGrid, T>>>(h2p, b2, z, N);

    // decoder (fp32 in from d_out, fp32 out): x_recon = z @ Wd + bd
    gemm_fp16<OUT_F, IN_F, false, false, true, false><<<592, T, smem3>>>(
        z, Wd, bd, out, N, nullptr, 0);
}

// round 11
// speedup vs baseline: 1.3539x; 1.0438x over previous
#include <cuda_runtime.h>
#include <cuda_fp16.h>
#include <cstdint>

#define IN_F   128
#define HID_F  128
#define OUT_F  64
#define MAX_N  100000
#define MAX_E  1600000

// ---------------- scratch (static device memory; no allocations) ----------------
__device__ float  g_dinv  [MAX_N];
__device__ int    g_cnt   [MAX_N];
__device__ int    g_rowptr[MAX_N + 1];
__device__ int    g_pos   [MAX_N];
__device__ int    g_col   [MAX_E];         // src id per CSR slot (4B)
__device__ int    g_bsum  [512];
__device__ __half g_h0s   [(size_t)MAX_N * HID_F];   // (x @ W1)*dinv      (fp16)
__device__ __half g_aggh  [(size_t)MAX_N * HID_F];   // relu(conv1 out)    (fp16)
__device__ __half g_h2s   [(size_t)MAX_N * OUT_F];   // (aggh @ W2)*dinv   (fp16)
__device__ int    g_is64;

// ---------------- zero counts + edge-index dtype detection ----------------------
__global__ void init_zero_detect(const unsigned int* __restrict__ w, int n) {
    int i = blockIdx.x * blockDim.x + threadIdx.x;
    if (i < n) g_cnt[i] = 0;
    if (i == 0) {
        int is64 = 1;
        for (int j = 1; j < 64; j += 2)
            if (w[j] != 0u) is64 = 0;
        g_is64 = is64;
    }
}

__device__ __forceinline__ void load_edge(const void* ei, int E, int i, int is64,
                                          int& s, int& d) {
    if (is64) {
        s = (int)((const long long*)ei)[i];
        d = (int)((const long long*)ei)[(size_t)E + i];
    } else {
        s = ((const int*)ei)[i];
        d = ((const int*)ei)[(size_t)E + i];
    }
}

__global__ void count_kernel(const void* __restrict__ ei, int E) {
    const int is64 = g_is64;
    int i = blockIdx.x * blockDim.x + threadIdx.x;
    if (i < E) {
        int d = is64 ? (int)((const long long*)ei)[(size_t)E + i]
                     : ((const int*)ei)[(size_t)E + i];
        atomicAdd(&g_cnt[d], 1);
    }
}

// ---------------- CSR scan chain ------------------------------------------------
__global__ void scan_block(int n) {
    __shared__ int sh[256];
    int tid = threadIdx.x;
    int i = blockIdx.x * 256 + tid;
    int v = (i < n) ? g_cnt[i] : 0;
    sh[tid] = v;
    __syncthreads();
#pragma unroll
    for (int off = 1; off < 256; off <<= 1) {
        int t = (tid >= off) ? sh[tid - off] : 0;
        __syncthreads();
        sh[tid] += t;
        __syncthreads();
    }
    if (i < n) g_rowptr[i] = sh[tid] - v;
    if (tid == 255) g_bsum[blockIdx.x] = sh[255];
}

// merged top-scan + add: block offset = sum of g_bsum[0..blockIdx)
__global__ void scan_add(int n, int E) {
    __shared__ int red[8];
    __shared__ int offsh;
    int tid = threadIdx.x;
    int v = 0;
    for (int j = tid; j < blockIdx.x; j += 256) v += g_bsum[j];
#pragma unroll
    for (int o = 16; o; o >>= 1) v += __shfl_down_sync(0xffffffffu, v, o);
    if ((tid & 31) == 0) red[tid >> 5] = v;
    __syncthreads();
    if (tid == 0) {
        int s = 0;
#pragma unroll
        for (int j = 0; j < 8; j++) s += red[j];
        offsh = s;
    }
    __syncthreads();
    int off = offsh;
    int i = blockIdx.x * 256 + tid;
    if (i < n) {
        int r = g_rowptr[i] + off;
        g_rowptr[i] = r;
        g_pos[i] = r;
        g_dinv[i] = rsqrtf((float)g_cnt[i] + 1.0f);
    }
    if (i == 0) g_rowptr[n] = E;
}

__global__ void fill_kernel(const void* __restrict__ ei, int E) {
    const int is64 = g_is64;
    int i = blockIdx.x * blockDim.x + threadIdx.x;
    if (i < E) {
        int s, d; load_edge(ei, E, i, is64, s, d);
        int idx = atomicAdd(&g_pos[d], 1);
        g_col[idx] = s;
    }
}

// ---------------- FP16 tensor-core GEMM ------------------------------------------
// C[M,NC] = A[M,K] @ W[K,NC] (+bias) (optionally * dinv[row]), fp32 accumulate.
// mma.m16n8k16.f16.f16.f32. 64-row tiles; 8 warps = 2 m-groups x 4 n-groups.
// SMEM (half2 words): Ws2 stride NCP2=NC+8 (mod32==8), As2 stride KP2=K/2+4 (mod32==4).
template<int K, int NC, bool A_HALF, bool OUT_HALF, bool BIAS, bool SCALE_OUT>
__global__ void __launch_bounds__(256) gemm_fp16(
        const void* __restrict__ Av, const float* __restrict__ W,
        const float* __restrict__ bias, void* __restrict__ Cv, int M) {
    constexpr int KP2  = K / 2 + 4;
    constexpr int NCP2 = NC + 8;
    constexpr int NT_W = NC / 32;

    extern __shared__ unsigned sh[];
    unsigned* Ws2 = sh;                       // (K/2) * NCP2 words
    unsigned* As2 = sh + (K / 2) * NCP2;      // 64 * KP2 words

    const int tid = threadIdx.x;

    // ---- stage W once: pack k-pairs into half2 words ----
    for (int i = tid; i < (K / 2) * (NC / 4); i += 256) {
        int kp = i / (NC / 4), n4 = i - kp * (NC / 4);
        float4 r0 = *(const float4*)(W + (size_t)(2 * kp) * NC + n4 * 4);
        float4 r1 = *(const float4*)(W + (size_t)(2 * kp + 1) * NC + n4 * 4);
        uint4 u;
        *(__half2*)&u.x = __floats2half2_rn(r0.x, r1.x);
        *(__half2*)&u.y = __floats2half2_rn(r0.y, r1.y);
        *(__half2*)&u.z = __floats2half2_rn(r0.z, r1.z);
        *(__half2*)&u.w = __floats2half2_rn(r0.w, r1.w);
        *(uint4*)(Ws2 + kp * NCP2 + n4 * 4) = u;
    }

    const int warp = tid >> 5, lane = tid & 31;
    const int g = lane >> 2, tg = lane & 3;
    const int mi = warp >> 2;
    const int ni = warp & 3;
    const int ntiles = (M + 63) >> 6;

    for (int tile = blockIdx.x; tile < ntiles; tile += gridDim.x) {
        const int row0 = tile << 6;
        __syncthreads();
        // ---- stage 64-row A tile ----
        constexpr int K8 = K / 8;
        for (int i = tid; i < 64 * K8; i += 256) {
            int r = i / K8, c8 = i - r * K8;
            uint4 u;
            if (A_HALF) {
                const __half* A = (const __half*)Av;
                if (row0 + r < M)
                    u = *(const uint4*)(A + (size_t)(row0 + r) * K + c8 * 8);
                else
                    u = make_uint4(0, 0, 0, 0);
            } else {
                const float* A = (const float*)Av;
                float4 v0 = {0.f, 0.f, 0.f, 0.f}, v1 = {0.f, 0.f, 0.f, 0.f};
                if (row0 + r < M) {
                    v0 = *(const float4*)(A + (size_t)(row0 + r) * K + c8 * 8);
                    v1 = *(const float4*)(A + (size_t)(row0 + r) * K + c8 * 8 + 4);
                }
                *(__half2*)&u.x = __floats2half2_rn(v0.x, v0.y);
                *(__half2*)&u.y = __floats2half2_rn(v0.z, v0.w);
                *(__half2*)&u.z = __floats2half2_rn(v1.x, v1.y);
                *(__half2*)&u.w = __floats2half2_rn(v1.z, v1.w);
            }
            *(uint4*)(As2 + r * KP2 + c8 * 4) = u;
        }
        __syncthreads();

        float acc[2][NT_W][4];
#pragma unroll
        for (int ms = 0; ms < 2; ms++)
#pragma unroll
            for (int t = 0; t < NT_W; t++)
#pragma unroll
                for (int v = 0; v < 4; v++) acc[ms][t][v] = 0.f;

        const unsigned* Arow0 = As2 + (mi * 32 + g) * KP2;
        const unsigned* Arow1 = Arow0 + 16 * KP2;
#pragma unroll
        for (int kp0 = 0; kp0 < K / 2; kp0 += 8) {      // 16 k per iter
            unsigned a[2][4];
            a[0][0] = Arow0[kp0 + tg];
            a[0][1] = Arow0[8 * KP2 + kp0 + tg];
            a[0][2] = Arow0[kp0 + tg + 4];
            a[0][3] = Arow0[8 * KP2 + kp0 + tg + 4];
            a[1][0] = Arow1[kp0 + tg];
            a[1][1] = Arow1[8 * KP2 + kp0 + tg];
            a[1][2] = Arow1[kp0 + tg + 4];
            a[1][3] = Arow1[8 * KP2 + kp0 + tg + 4];
#pragma unroll
            for (int t = 0; t < NT_W; t++) {
                int n0 = ni * (NT_W * 8) + t * 8;
                unsigned b0 = Ws2[(kp0 + tg) * NCP2 + n0 + g];
                unsigned b1 = Ws2[(kp0 + tg + 4) * NCP2 + n0 + g];
#pragma unroll
                for (int ms = 0; ms < 2; ms++) {
                    asm volatile(
                        "mma.sync.aligned.m16n8k16.row.col.f32.f16.f16.f32 "
                        "{%0,%1,%2,%3},{%4,%5,%6,%7},{%8,%9},{%0,%1,%2,%3};\n"
                        : "+f"(acc[ms][t][0]), "+f"(acc[ms][t][1]),
                          "+f"(acc[ms][t][2]), "+f"(acc[ms][t][3])
                        : "r"(a[ms][0]), "r"(a[ms][1]), "r"(a[ms][2]), "r"(a[ms][3]),
                          "r"(b0), "r"(b1));
                }
            }
        }

#pragma unroll
        for (int ms = 0; ms < 2; ms++) {
            const int r0 = row0 + mi * 32 + ms * 16 + g;
            const int r1 = r0 + 8;
            float s0 = 1.f, s1 = 1.f;
            if (SCALE_OUT) {
                if (r0 < M) s0 = g_dinv[r0];
                if (r1 < M) s1 = g_dinv[r1];
            }
#pragma unroll
            for (int t = 0; t < NT_W; t++) {
                int n0 = ni * (NT_W * 8) + t * 8 + 2 * tg;
                float bx = 0.f, by = 0.f;
                if (BIAS) { bx = bias[n0]; by = bias[n0 + 1]; }
                if (OUT_HALF) {
                    __half* C = (__half*)Cv;
                    if (r0 < M)
                        *(__half2*)(C + (size_t)r0 * NC + n0) = __floats2half2_rn(
                            (acc[ms][t][0] + bx) * s0, (acc[ms][t][1] + by) * s0);
                    if (r1 < M)
                        *(__half2*)(C + (size_t)r1 * NC + n0) = __floats2half2_rn(
                            (acc[ms][t][2] + bx) * s1, (acc[ms][t][3] + by) * s1);
                } else {
                    float* C = (float*)Cv;
                    if (r0 < M) {
                        float2 o = {(acc[ms][t][0] + bx) * s0, (acc[ms][t][1] + by) * s0};
                        *(float2*)(C + (size_t)r0 * NC + n0) = o;
                    }
                    if (r1 < M) {
                        float2 o = {(acc[ms][t][2] + bx) * s1, (acc[ms][t][3] + by) * s1};
                        *(float2*)(C + (size_t)r1 * NC + n0) = o;
                    }
                }
            }
        }
    }
}

// ------------- CSR gather over pre-scaled features (warp per destination row) ---
// hs[i] = h[i]*dinv[i] (fp16). out[i] = dv*(sum_nbr hs[s] + hs[i]) + bias ; relu?
template<int F, bool RELU, bool OUT_HALF>
__global__ void __launch_bounds__(256) gather_agg(
        const __half* __restrict__ hs, const float* __restrict__ bias,
        void* __restrict__ out, int Nn) {
    int w = (blockIdx.x * 256 + threadIdx.x) >> 5;
    int lane = threadIdx.x & 31;
    if (w >= Nn) return;
    constexpr int V = F / 32;               // halves per lane: 4 or 2

    float dv = g_dinv[w];
    float acc[V];

    // self-loop (pre-scaled row; dv applied at the end)
    {
        const __half* hp = hs + (size_t)w * F + lane * V;
        if (V == 4) {
            uint2 u = *(const uint2*)hp;
            float2 f0 = __half22float2(*(const __half2*)&u.x);
            float2 f1 = __half22float2(*(const __half2*)&u.y);
            acc[0] = f0.x; acc[1] = f0.y; acc[2] = f1.x; acc[3] = f1.y;
        } else {
            unsigned u = *(const unsigned*)hp;
            float2 f0 = __half22float2(*(const __half2*)&u);
            acc[0] = f0.x; acc[1] = f0.y;
        }
    }

    int beg = g_rowptr[w], end = g_rowptr[w + 1];
#pragma unroll 8
    for (int j = beg; j < end; j++) {
        int s = g_col[j];                   // 4B warp-uniform broadcast load
        const __half* hp = hs + (size_t)s * F + lane * V;
        if (V == 4) {
            uint2 u = *(const uint2*)hp;
            float2 f0 = __half22float2(*(const __half2*)&u.x);
            float2 f1 = __half22float2(*(const __half2*)&u.y);
            acc[0] += f0.x; acc[1] += f0.y; acc[2] += f1.x; acc[3] += f1.y;
        } else {
            unsigned u = *(const unsigned*)hp;
            float2 f0 = __half22float2(*(const __half2*)&u);
            acc[0] += f0.x; acc[1] += f0.y;
        }
    }

    float res[V];
#pragma unroll
    for (int v = 0; v < V; v++) {
        res[v] = fmaf(acc[v], dv, bias[lane * V + v]);
        if (RELU) res[v] = fmaxf(res[v], 0.f);
    }

    if (OUT_HALF) {
        __half* op = (__half*)out + (size_t)w * F + lane * V;
        if (V == 4) {
            uint2 u;
            *(__half2*)&u.x = __floats2half2_rn(res[0], res[1]);
            *(__half2*)&u.y = __floats2half2_rn(res[2], res[3]);
            *(uint2*)op = u;
        } else {
            __half2 u = __floats2half2_rn(res[0], res[1]);
            *(__half2*)op = u;
        }
    } else {
        float* op = (float*)out + (size_t)w * F + lane * V;
        if (V == 4) { float4 o = {res[0], res[1], res[2], res[3]}; *(float4*)op = o; }
        else        { float2 o = {res[0], res[1]};                 *(float2*)op = o; }
    }
}

// --------------------------------- launch ---------------------------------------
extern "C" void kernel_launch(void* const* d_in, const int* in_sizes, int n_in,
                              void* d_out, int out_size) {
    const float* x  = (const float*)d_in[0];
    const void*  ei = d_in[1];
    const float* W1 = (const float*)d_in[2];
    const float* b1 = (const float*)d_in[3];
    const float* W2 = (const float*)d_in[4];
    const float* b2 = (const float*)d_in[5];
    const float* Wd = (const float*)d_in[6];
    const float* bd = (const float*)d_in[7];

    const int N = in_sizes[0] / IN_F;     // 100000
    const int E = in_sizes[1] / 2;        // 1.6M

    float* out = (float*)d_out;           // x_recon [N, IN_F]
    float* z   = out + (size_t)N * IN_F;  // z       [N, OUT_F]

    __half *h0sp, *agghp, *h2sp;
    cudaGetSymbolAddress((void**)&h0sp,  g_h0s);
    cudaGetSymbolAddress((void**)&agghp, g_aggh);
    cudaGetSymbolAddress((void**)&h2sp,  g_h2s);

    // smem (bytes): Ws2 (K/2)*(NC+8) + As2 64*(K/2+4), 4B words
    const int smem1 = ((IN_F  / 2) * (HID_F + 8) + 64 * (IN_F  / 2 + 4)) * 4;  // 52224
    const int smem2 = ((HID_F / 2) * (OUT_F + 8) + 64 * (HID_F / 2 + 4)) * 4;  // 35840
    const int smem3 = ((OUT_F / 2) * (IN_F  + 8) + 64 * (OUT_F / 2 + 4)) * 4;  // 26624
    cudaFuncSetAttribute(gemm_fp16<IN_F, HID_F, false, true, false, true>,
                         cudaFuncAttributeMaxDynamicSharedMemorySize, smem1);
    cudaFuncSetAttribute(gemm_fp16<HID_F, OUT_F, true, true, false, true>,
                         cudaFuncAttributeMaxDynamicSharedMemorySize, smem2);
    cudaFuncSetAttribute(gemm_fp16<OUT_F, IN_F, false, false, true, false>,
                         cudaFuncAttributeMaxDynamicSharedMemorySize, smem3);

    const int T = 256;
    const int nScanBlocks = (N + 255) / 256;
    const int aggGrid = (N * 32 + T - 1) / T;     // warp per node

    // degrees + dinv (needed by GEMM1's epilogue scaling)
    init_zero_detect<<<nScanBlocks, 256>>>((const unsigned int*)ei, N);
    count_kernel<<<(E + T - 1) / T, T>>>(ei, E);
    scan_block<<<nScanBlocks, 256>>>(N);
    scan_add<<<nScanBlocks, 256>>>(N, E);

    // layer-1 GEMM (fp32 in, fp16 out, *dinv): h0s = (x @ W1) * dinv
    gemm_fp16<IN_F, HID_F, false, true, false, true><<<592, T, smem1>>>(
        x, W1, nullptr, h0sp, N);

    // CSR adjacency fill (4B src ids)
    fill_kernel<<<(E + T - 1) / T, T>>>(ei, E);

    // layer-1 aggregation: aggh = relu(dinv*(sum h0s + self) + b1)  (fp16)
    gather_agg<HID_F, true, true><<<aggGrid, T>>>(h0sp, b1, agghp, N);

    // layer-2 GEMM (fp16 in, fp16 out, *dinv): h2s = (aggh @ W2) * dinv
    gemm_fp16<HID_F, OUT_F, true, true, false, true><<<592, T, smem2>>>(
        agghp, W2, nullptr, h2sp, N);

    // layer-2 aggregation: z = dinv*(sum h2s + self) + b2  (fp32, into d_out)
    gather_agg<OUT_F, false, false><<<aggGrid, T>>>(h2sp, b2, z, N);

    // decoder (fp32 in from d_out, fp32 out): x_recon = z @ Wd + bd
    gemm_fp16<OUT_F, IN_F, false, false, true, false><<<592, T, smem3>>>(
        z, Wd, bd, out, N);
}